// round 2
// baseline (speedup 1.0000x reference)
#include <cuda_runtime.h>
#include <math.h>

// Problem constants
#define NB   4
#define LL   4096
#define SS   256
#define CC   256
#define HH   256
#define FCn  8
#define SCn  32
#define MM   32      // NB*FCn
#define H2   512
#define KK   256     // inner dim of all GEMMs

// Scratch (device globals; no dynamic allocation allowed)
__device__ float g_c1[NB * SS * H2];        // center1 @ W1^T + b1   (2 MB)
__device__ float g_cpN[MM * SS * SCn];      // normalized c_point    (1 MB)
__device__ float g_cv [MM * SS * SCn];      // c_value               (1 MB)
__device__ float g_x0p[NB * LL * HH];       // x0 @ W0^T + b0        (16.8 MB)
__device__ float g_disp[NB * LL * HH];      // dispatched            (16.8 MB)

// ---------------------------------------------------------------------------
// Generic GEMM:  C[R][Hout] = A[R][256] @ B[Hout][256]^T + bias
// block tile 64x64, 256 threads, 4x4 micro-tile, k-chunks of 32
// ---------------------------------------------------------------------------
__global__ __launch_bounds__(256) void gemm_nt64(
    const float* __restrict__ A, const float* __restrict__ B,
    const float* __restrict__ bias, float* __restrict__ C, int Hout)
{
    __shared__ float as[32][68];   // [k][r], padded
    __shared__ float bs[32][68];   // [k][h], padded

    const int r0 = blockIdx.x * 64;
    const int h0 = blockIdx.y * 64;
    const int tid = threadIdx.x;
    const int tr = tid & 15;       // row group 0..15
    const int tc = tid >> 4;       // col group 0..15

    float acc[4][4] = {};

    const int k4 = (tid & 7) * 4;  // 0..28
    const int rl = tid >> 3;       // 0..31

    for (int k0 = 0; k0 < KK; k0 += 32) {
        // load A tile (64 x 32) and B tile (64 x 32), coalesced global reads
        #pragma unroll
        for (int rr = 0; rr < 64; rr += 32) {
            float4 v = *(const float4*)&A[(size_t)(r0 + rl + rr) * KK + k0 + k4];
            as[k4 + 0][rl + rr] = v.x;
            as[k4 + 1][rl + rr] = v.y;
            as[k4 + 2][rl + rr] = v.z;
            as[k4 + 3][rl + rr] = v.w;
        }
        #pragma unroll
        for (int rr = 0; rr < 64; rr += 32) {
            float4 v = *(const float4*)&B[(size_t)(h0 + rl + rr) * KK + k0 + k4];
            bs[k4 + 0][rl + rr] = v.x;
            bs[k4 + 1][rl + rr] = v.y;
            bs[k4 + 2][rl + rr] = v.z;
            bs[k4 + 3][rl + rr] = v.w;
        }
        __syncthreads();

        #pragma unroll
        for (int kk = 0; kk < 32; kk++) {
            float4 a4 = *(const float4*)&as[kk][tr * 4];
            float4 b4 = *(const float4*)&bs[kk][tc * 4];
            float a[4] = {a4.x, a4.y, a4.z, a4.w};
            float b[4] = {b4.x, b4.y, b4.z, b4.w};
            #pragma unroll
            for (int i = 0; i < 4; i++)
                #pragma unroll
                for (int j = 0; j < 4; j++)
                    acc[i][j] = fmaf(a[i], b[j], acc[i][j]);
        }
        __syncthreads();
    }

    float4 bb = *(const float4*)&bias[h0 + tc * 4];
    #pragma unroll
    for (int i = 0; i < 4; i++) {
        int row = r0 + tr * 4 + i;
        float4 o;
        o.x = acc[i][0] + bb.x;
        o.y = acc[i][1] + bb.y;
        o.z = acc[i][2] + bb.z;
        o.w = acc[i][3] + bb.w;
        *(float4*)&C[(size_t)row * Hout + h0 + tc * 4] = o;
    }
}

// ---------------------------------------------------------------------------
// Split c1 into c_point (l2-normalized) / c_value, regrouped layout [m][s][32]
// one warp per (m, s)
// ---------------------------------------------------------------------------
__global__ __launch_bounds__(256) void center_norm_kernel()
{
    int w    = (blockIdx.x * blockDim.x + threadIdx.x) >> 5;  // 0..8191
    int lane = threadIdx.x & 31;
    int m = w >> 8;            // 0..31
    int s = w & 255;
    int n = m >> 3, f = m & 7;

    const float* row = &g_c1[((size_t)(n * SS + s)) * H2 + f * 64];
    float p = row[lane];
    float v = row[32 + lane];

    float sq = p * p;
    #pragma unroll
    for (int off = 16; off; off >>= 1)
        sq += __shfl_xor_sync(0xffffffffu, sq, off);

    float d = fmaxf(sqrtf(sq), 1e-12f);
    size_t o = ((size_t)(m * SS + s)) * SCn + lane;
    g_cpN[o] = p / d;
    g_cv [o] = v;
}

// ---------------------------------------------------------------------------
// Fused: l2-normalize x0p chunk, sim vs 256 centers, affine-argmax, sigmoid,
// gather c_value, write dispatched.  block = (m, 128-row l-tile), 256 threads.
// ---------------------------------------------------------------------------
__global__ __launch_bounds__(256) void sim_dispatch_kernel(
    const float* __restrict__ alpha_p, const float* __restrict__ beta_p)
{
    __shared__ float cps[256 * 36];   // [s][k] padded to 36 (16B-aligned rows)

    const int m  = blockIdx.y;        // 0..31
    const int n  = m >> 3, f = m & 7;
    const int l0 = blockIdx.x * 128;
    const int tid  = threadIdx.x;
    const int warp = tid >> 5;
    const int lane = tid & 31;

    // load normalized c_point tile: g_cpN[m] is contiguous 8192 floats
    const float* cpm = &g_cpN[(size_t)m * SS * SCn];
    for (int idx = tid; idx < SS * SCn; idx += 256) {
        int s = idx >> 5, k = idx & 31;
        cps[s * 36 + k] = cpm[idx];
    }
    __syncthreads();

    const float alpha = alpha_p[0];
    const float beta  = beta_p[0];
    const float* cvm  = &g_cv[(size_t)m * SS * SCn];

    for (int rr = 0; rr < 16; rr++) {
        int l = l0 + warp * 16 + rr;
        const float* xrow = &g_x0p[((size_t)(n * LL + l)) * HH + f * SCn];
        float x = xrow[lane];

        float sq = x * x;
        #pragma unroll
        for (int off = 16; off; off >>= 1)
            sq += __shfl_xor_sync(0xffffffffu, sq, off);
        float xn = x / fmaxf(sqrtf(sq), 1e-12f);

        float acc[8] = {0.f, 0.f, 0.f, 0.f, 0.f, 0.f, 0.f, 0.f};
        #pragma unroll
        for (int kq = 0; kq < 8; kq++) {
            float x0_ = __shfl_sync(0xffffffffu, xn, kq * 4 + 0);
            float x1_ = __shfl_sync(0xffffffffu, xn, kq * 4 + 1);
            float x2_ = __shfl_sync(0xffffffffu, xn, kq * 4 + 2);
            float x3_ = __shfl_sync(0xffffffffu, xn, kq * 4 + 3);
            #pragma unroll
            for (int t = 0; t < 8; t++) {
                int s = lane + t * 32;
                float4 cp = *(const float4*)&cps[s * 36 + kq * 4];
                float a = acc[t];
                a = fmaf(x0_, cp.x, a);
                a = fmaf(x1_, cp.y, a);
                a = fmaf(x2_, cp.z, a);
                a = fmaf(x3_, cp.w, a);
                acc[t] = a;
            }
        }

        // max/argmax of affine value (sigmoid is strictly monotonic,
        // so ordering — including ties — is preserved; apply sigmoid once)
        float vbest = -INFINITY; int sbest = 0;
        #pragma unroll
        for (int t = 0; t < 8; t++) {
            float v = fmaf(alpha, acc[t], beta);
            if (v > vbest) { vbest = v; sbest = lane + t * 32; }
        }
        #pragma unroll
        for (int off = 16; off; off >>= 1) {
            float v2 = __shfl_xor_sync(0xffffffffu, vbest, off);
            int   s2 = __shfl_xor_sync(0xffffffffu, sbest, off);
            if (v2 > vbest || (v2 == vbest && s2 < sbest)) { vbest = v2; sbest = s2; }
        }

        float mval = 1.f / (1.f + __expf(-vbest));
        float out  = mval * __ldg(&cvm[sbest * SCn + lane]);
        g_disp[((size_t)(n * LL + l)) * HH + f * SCn + lane] = out;
    }
}

// ---------------------------------------------------------------------------
extern "C" void kernel_launch(void* const* d_in, const int* in_sizes, int n_in,
                              void* d_out, int out_size)
{
    const float* x0      = (const float*)d_in[0];
    const float* center1 = (const float*)d_in[1];
    const float* W0      = (const float*)d_in[2];
    const float* b0      = (const float*)d_in[3];
    const float* W1      = (const float*)d_in[4];
    const float* b1      = (const float*)d_in[5];
    const float* Wm      = (const float*)d_in[6];
    const float* bm      = (const float*)d_in[7];
    const float* alpha   = (const float*)d_in[8];
    const float* beta    = (const float*)d_in[9];
    float* out           = (float*)d_out;

    float* c1p;   cudaGetSymbolAddress((void**)&c1p,  g_c1);
    float* x0pp;  cudaGetSymbolAddress((void**)&x0pp, g_x0p);
    float* dispp; cudaGetSymbolAddress((void**)&dispp, g_disp);

    // K1: c1 = center1 @ W1^T + b1   (1024 x 512 x 256)
    gemm_nt64<<<dim3(1024 / 64, H2 / 64), 256>>>(center1, W1, b1, c1p, H2);

    // K1b: normalize c_point, split c_value
    center_norm_kernel<<<1024, 256>>>();

    // K2: x0p = x0 @ W0^T + b0       (16384 x 256 x 256)
    gemm_nt64<<<dim3((NB * LL) / 64, HH / 64), 256>>>(x0, W0, b0, x0pp, HH);

    // K3: normalize + sim + argmax + sigmoid + gather -> dispatched
    sim_dispatch_kernel<<<dim3(LL / 128, MM), 256>>>(alpha, beta);

    // K4: out = dispatched @ Wm^T + bm  (16384 x 256 x 256)
    gemm_nt64<<<dim3((NB * LL) / 64, HH / 64), 256>>>(dispp, Wm, bm, out, HH);
}

// round 3
// speedup vs baseline: 1.0336x; 1.0336x over previous
#include <cuda_runtime.h>
#include <math.h>

// Problem constants
#define NB   4
#define LL   4096
#define SS   256
#define HH   256
#define FCn  8
#define SCn  32
#define MM   32      // NB*FCn
#define H2   512
#define KK   256     // inner dim of dense GEMMs

typedef unsigned long long u64;

// Scratch (device globals; no dynamic allocation allowed)
__device__ float g_c1[NB * SS * H2];        // center1 @ W1^T + b1   (2 MB)
__device__ float g_cpN[MM * SS * SCn];      // normalized c_point    (1 MB)
__device__ float g_cv [MM * SS * SCn];      // c_value               (1 MB)
__device__ float g_x0p[NB * LL * HH];       // x0 @ W0^T + b0        (16.8 MB)
__device__ float g_disp[NB * LL * HH];      // dispatched            (16.8 MB)

// ---------------------------------------------------------------------------
// packed f32x2 helpers (FFMA2 — only reachable via PTX)
// ---------------------------------------------------------------------------
__device__ __forceinline__ u64 ffma2(u64 a, u64 b, u64 c) {
    u64 d;
    asm("fma.rn.f32x2 %0, %1, %2, %3;" : "=l"(d) : "l"(a), "l"(b), "l"(c));
    return d;
}
__device__ __forceinline__ u64 pack2(float x, float y) {
    u64 r;
    asm("mov.b64 %0, {%1, %2};" : "=l"(r) : "f"(x), "f"(y));
    return r;
}
__device__ __forceinline__ float2 unpack2(u64 v) {
    float2 f;
    asm("mov.b64 {%0, %1}, %2;" : "=f"(f.x), "=f"(f.y) : "l"(v));
    return f;
}

// ---------------------------------------------------------------------------
// Dense GEMM:  C[R][Hout] = A[R][256] @ B[Hout][256]^T + bias
// block tile 128x64, 256 threads, 8x4 micro-tile (l-pairs packed f32x2),
// k-chunks of 32, k-major smem.
// ---------------------------------------------------------------------------
__global__ __launch_bounds__(256) void gemm_nt128(
    const float* __restrict__ A, const float* __restrict__ B,
    const float* __restrict__ bias, float* __restrict__ C, int Hout)
{
    __shared__ __align__(16) float as[32][132];   // [k][l], pad keeps 16B align
    __shared__ __align__(16) float bs[32][68];    // [k][h]

    const int r0 = blockIdx.x * 128;
    const int h0 = blockIdx.y * 64;
    const int tid = threadIdx.x;
    const int tc = tid & 15;        // h-group (4 h)
    const int tr = tid >> 4;        // l-group (8 l)

    const int k4 = (tid & 7) * 4;   // 0..28
    const int rl = tid >> 3;        // 0..31

    u64 acc[4][4];
    #pragma unroll
    for (int p = 0; p < 4; p++)
        #pragma unroll
        for (int j = 0; j < 4; j++) acc[p][j] = 0ull;

    for (int k0 = 0; k0 < KK; k0 += 32) {
        // load A tile (128 x 32) transposed to [k][l]
        #pragma unroll
        for (int it = 0; it < 4; it++) {
            int row = rl + it * 32;
            float4 v = *(const float4*)&A[(size_t)(r0 + row) * KK + k0 + k4];
            as[k4 + 0][row] = v.x;
            as[k4 + 1][row] = v.y;
            as[k4 + 2][row] = v.z;
            as[k4 + 3][row] = v.w;
        }
        // load B tile (64 x 32) transposed to [k][h]
        #pragma unroll
        for (int it = 0; it < 2; it++) {
            int h = rl + it * 32;
            float4 v = *(const float4*)&B[(size_t)(h0 + h) * KK + k0 + k4];
            bs[k4 + 0][h] = v.x;
            bs[k4 + 1][h] = v.y;
            bs[k4 + 2][h] = v.z;
            bs[k4 + 3][h] = v.w;
        }
        __syncthreads();

        #pragma unroll
        for (int kk = 0; kk < 32; kk++) {
            ulonglong2 a01 = *(const ulonglong2*)&as[kk][tr * 8];
            ulonglong2 a23 = *(const ulonglong2*)&as[kk][tr * 8 + 4];
            float4 bv = *(const float4*)&bs[kk][tc * 4];
            u64 ap[4] = {a01.x, a01.y, a23.x, a23.y};
            u64 b0 = pack2(bv.x, bv.x);
            u64 b1 = pack2(bv.y, bv.y);
            u64 b2 = pack2(bv.z, bv.z);
            u64 b3 = pack2(bv.w, bv.w);
            #pragma unroll
            for (int p = 0; p < 4; p++) {
                acc[p][0] = ffma2(ap[p], b0, acc[p][0]);
                acc[p][1] = ffma2(ap[p], b1, acc[p][1]);
                acc[p][2] = ffma2(ap[p], b2, acc[p][2]);
                acc[p][3] = ffma2(ap[p], b3, acc[p][3]);
            }
        }
        __syncthreads();
    }

    float4 bb = *(const float4*)&bias[h0 + tc * 4];
    #pragma unroll
    for (int p = 0; p < 4; p++) {
        float2 f0 = unpack2(acc[p][0]);
        float2 f1 = unpack2(acc[p][1]);
        float2 f2 = unpack2(acc[p][2]);
        float2 f3 = unpack2(acc[p][3]);
        int row0 = r0 + tr * 8 + 2 * p;
        float4 o0 = make_float4(f0.x + bb.x, f1.x + bb.y, f2.x + bb.z, f3.x + bb.w);
        float4 o1 = make_float4(f0.y + bb.x, f1.y + bb.y, f2.y + bb.z, f3.y + bb.w);
        *(float4*)&C[(size_t)row0 * Hout + h0 + tc * 4] = o0;
        *(float4*)&C[(size_t)(row0 + 1) * Hout + h0 + tc * 4] = o1;
    }
}

// ---------------------------------------------------------------------------
// Split c1 into c_point (l2-normalized) / c_value, regrouped layout [m][s][32]
// ---------------------------------------------------------------------------
__global__ __launch_bounds__(256) void center_norm_kernel()
{
    int w    = (blockIdx.x * blockDim.x + threadIdx.x) >> 5;  // 0..8191
    int lane = threadIdx.x & 31;
    int m = w >> 8;
    int s = w & 255;
    int n = m >> 3, f = m & 7;

    const float* row = &g_c1[((size_t)(n * SS + s)) * H2 + f * 64];
    float p = row[lane];
    float v = row[32 + lane];

    float sq = p * p;
    #pragma unroll
    for (int off = 16; off; off >>= 1)
        sq += __shfl_xor_sync(0xffffffffu, sq, off);

    float d = fmaxf(sqrtf(sq), 1e-12f);
    size_t o = ((size_t)(m * SS + s)) * SCn + lane;
    g_cpN[o] = p / d;
    g_cv [o] = v;
}

// ---------------------------------------------------------------------------
// Fused sim + argmax + gather, register-tiled:
// block = (m, 128-l tile), 256 threads. 8l x 4s micro-tile, K=32 resident.
// s processed in 2 smem halves x 2 register chunks of 64.
// ---------------------------------------------------------------------------
__global__ __launch_bounds__(256) void sim_dispatch2(
    const float* __restrict__ alpha_p, const float* __restrict__ beta_p)
{
    __shared__ __align__(16) float xs[32][132];   // [k][l] normalized x
    __shared__ __align__(16) float cs[32][132];   // [k][s-half]
    __shared__ float smv[128];
    __shared__ int   sms[128];

    const int m  = blockIdx.y;
    const int n  = m >> 3, f = m & 7;
    const int l0 = blockIdx.x * 128;
    const int tid  = threadIdx.x;
    const int warp = tid >> 5;
    const int lane = tid & 31;
    const int tc = tid & 15;
    const int tr = tid >> 4;

    // load + l2-normalize 128 x-rows (one warp per 16 rows, lane = k)
    #pragma unroll 4
    for (int i = 0; i < 16; i++) {
        int row = warp * 16 + i;
        float x = g_x0p[((size_t)(n * LL + l0 + row)) * HH + f * SCn + lane];
        float sq = x * x;
        #pragma unroll
        for (int off = 16; off; off >>= 1)
            sq += __shfl_xor_sync(0xffffffffu, sq, off);
        xs[lane][row] = x / fmaxf(sqrtf(sq), 1e-12f);
    }

    const float alpha = alpha_p[0];
    const float beta  = beta_p[0];

    float vbest[8];
    int   sbest[8];
    #pragma unroll
    for (int r = 0; r < 8; r++) { vbest[r] = -INFINITY; sbest[r] = 0; }

    const float* cpm = &g_cpN[(size_t)m * SS * SCn];

    #pragma unroll 1
    for (int half = 0; half < 2; half++) {
        __syncthreads();   // first pass: xs ready; later: cs no longer read
        // load 128-s half of c_point, transposed to [k][s]
        const float* cph = cpm + half * 128 * SCn;
        #pragma unroll
        for (int it = 0; it < 16; it++) {
            int idx = tid + it * 256;
            cs[idx & 31][idx >> 5] = cph[idx];
        }
        __syncthreads();

        #pragma unroll 1
        for (int chunk = 0; chunk < 2; chunk++) {
            const int sbase = half * 128 + chunk * 64 + tc * 4;
            u64 acc[4][4];
            #pragma unroll
            for (int p = 0; p < 4; p++)
                #pragma unroll
                for (int j = 0; j < 4; j++) acc[p][j] = 0ull;

            #pragma unroll
            for (int kk = 0; kk < 32; kk++) {
                ulonglong2 a01 = *(const ulonglong2*)&xs[kk][tr * 8];
                ulonglong2 a23 = *(const ulonglong2*)&xs[kk][tr * 8 + 4];
                float4 bv = *(const float4*)&cs[kk][chunk * 64 + tc * 4];
                u64 ap[4] = {a01.x, a01.y, a23.x, a23.y};
                u64 b0 = pack2(bv.x, bv.x);
                u64 b1 = pack2(bv.y, bv.y);
                u64 b2 = pack2(bv.z, bv.z);
                u64 b3 = pack2(bv.w, bv.w);
                #pragma unroll
                for (int p = 0; p < 4; p++) {
                    acc[p][0] = ffma2(ap[p], b0, acc[p][0]);
                    acc[p][1] = ffma2(ap[p], b1, acc[p][1]);
                    acc[p][2] = ffma2(ap[p], b2, acc[p][2]);
                    acc[p][3] = ffma2(ap[p], b3, acc[p][3]);
                }
            }

            // affine + running argmax (sigmoid applied once at the end;
            // alpha sign handled because we compare the affine value itself)
            #pragma unroll
            for (int p = 0; p < 4; p++) {
                #pragma unroll
                for (int j = 0; j < 4; j++) {
                    float2 f2 = unpack2(acc[p][j]);
                    float v0 = fmaf(alpha, f2.x, beta);
                    float v1 = fmaf(alpha, f2.y, beta);
                    int s = sbase + j;
                    if (v0 > vbest[2 * p])     { vbest[2 * p] = v0;     sbest[2 * p] = s; }
                    if (v1 > vbest[2 * p + 1]) { vbest[2 * p + 1] = v1; sbest[2 * p + 1] = s; }
                }
            }
        }
    }

    // reduce across the 16 tc-threads sharing each l-row (stay in 16-lane group)
    #pragma unroll
    for (int r = 0; r < 8; r++) {
        #pragma unroll
        for (int off = 8; off; off >>= 1) {
            float v2 = __shfl_xor_sync(0xffffffffu, vbest[r], off);
            int   s2 = __shfl_xor_sync(0xffffffffu, sbest[r], off);
            if (v2 > vbest[r] || (v2 == vbest[r] && s2 < sbest[r])) {
                vbest[r] = v2; sbest[r] = s2;
            }
        }
    }
    if (tc == 0) {
        #pragma unroll
        for (int r = 0; r < 8; r++) {
            int row = tr * 8 + r;
            smv[row] = 1.f / (1.f + __expf(-vbest[r]));
            sms[row] = sbest[r];
        }
    }
    __syncthreads();

    // gather + scale + write dispatched (coalesced 128B rows)
    const float* cvm = &g_cv[(size_t)m * SS * SCn];
    #pragma unroll
    for (int it = 0; it < 16; it++) {
        int idx = tid + it * 256;
        int row = idx >> 5, k = idx & 31;
        float out = smv[row] * __ldg(&cvm[sms[row] * SCn + k]);
        g_disp[((size_t)(n * LL + l0 + row)) * HH + f * SCn + k] = out;
    }
}

// ---------------------------------------------------------------------------
extern "C" void kernel_launch(void* const* d_in, const int* in_sizes, int n_in,
                              void* d_out, int out_size)
{
    const float* x0      = (const float*)d_in[0];
    const float* center1 = (const float*)d_in[1];
    const float* W0      = (const float*)d_in[2];
    const float* b0      = (const float*)d_in[3];
    const float* W1      = (const float*)d_in[4];
    const float* b1      = (const float*)d_in[5];
    const float* Wm      = (const float*)d_in[6];
    const float* bm      = (const float*)d_in[7];
    const float* alpha   = (const float*)d_in[8];
    const float* beta    = (const float*)d_in[9];
    float* out           = (float*)d_out;

    float* c1p;   cudaGetSymbolAddress((void**)&c1p,  g_c1);
    float* x0pp;  cudaGetSymbolAddress((void**)&x0pp, g_x0p);
    float* dispp; cudaGetSymbolAddress((void**)&dispp, g_disp);

    // K1: c1 = center1 @ W1^T + b1   (1024 x 512 x 256)
    gemm_nt128<<<dim3(1024 / 128, H2 / 64), 256>>>(center1, W1, b1, c1p, H2);

    // K1b: normalize c_point, split c_value
    center_norm_kernel<<<1024, 256>>>();

    // K2: x0p = x0 @ W0^T + b0       (16384 x 256 x 256)
    gemm_nt128<<<dim3((NB * LL) / 128, HH / 64), 256>>>(x0, W0, b0, x0pp, HH);

    // K3: normalize + sim + argmax + sigmoid + gather -> dispatched
    sim_dispatch2<<<dim3(LL / 128, MM), 256>>>(alpha, beta);

    // K4: out = dispatched @ Wm^T + bm  (16384 x 256 x 256)
    gemm_nt128<<<dim3((NB * LL) / 128, HH / 64), 256>>>(dispp, Wm, bm, out, HH);
}

// round 4
// speedup vs baseline: 1.3825x; 1.3376x over previous
#include <cuda_runtime.h>
#include <math.h>

// Problem constants
#define NB   4
#define LL   4096
#define SS   256
#define HH   256
#define FCn  8
#define SCn  32
#define MM   32      // NB*FCn
#define H2   512
#define KK   256     // inner dim of dense GEMMs

typedef unsigned long long u64;

// Scratch (device globals; no dynamic allocation allowed)
__device__ float g_c1[NB * SS * H2];        // center1 @ W1^T + b1   (2 MB)
__device__ float g_cpN[MM * SS * SCn];      // normalized c_point    (1 MB)
__device__ float g_cv [MM * SS * SCn];      // c_value               (1 MB)
__device__ float g_x0p[NB * LL * HH];       // x0 @ W0^T + b0        (16.8 MB)
__device__ float g_disp[NB * LL * HH];      // dispatched            (16.8 MB)

// ---------------------------------------------------------------------------
// packed f32x2 helpers (FFMA2 — only reachable via PTX)
// ---------------------------------------------------------------------------
__device__ __forceinline__ u64 ffma2(u64 a, u64 b, u64 c) {
    u64 d;
    asm("fma.rn.f32x2 %0, %1, %2, %3;" : "=l"(d) : "l"(a), "l"(b), "l"(c));
    return d;
}
__device__ __forceinline__ u64 pack2(float x, float y) {
    u64 r;
    asm("mov.b64 %0, {%1, %2};" : "=l"(r) : "f"(x), "f"(y));
    return r;
}
__device__ __forceinline__ float2 unpack2(u64 v) {
    float2 f;
    asm("mov.b64 {%0, %1}, %2;" : "=f"(f.x), "=f"(f.y) : "l"(v));
    return f;
}

// ---------------------------------------------------------------------------
// Dense GEMM:  C[R][Hout] = A[R][256] @ B[Hout][256]^T + bias
// block tile 128 x NT, 256 threads, 8l x (NT/16)s micro-tile,
// l-pairs packed f32x2, k-chunks of 32, k-major smem, unroll-8 inner loop.
// ---------------------------------------------------------------------------
template<int NT>
__global__ __launch_bounds__(256, 2) void gemm_nt(
    const float* __restrict__ A, const float* __restrict__ B,
    const float* __restrict__ bias, float* __restrict__ C, int Hout)
{
    constexpr int SN = NT / 16;                  // s per thread (4 or 8)
    __shared__ __align__(16) float as[32][132];  // [k][l]
    __shared__ __align__(16) float bs[32][NT + 4];

    const int r0 = blockIdx.x * 128;
    const int h0 = blockIdx.y * NT;
    const int tid = threadIdx.x;
    const int tc = tid & 15;        // h-group (SN cols)
    const int tr = tid >> 4;        // l-group (8 rows)

    const int k4 = (tid & 7) * 4;   // 0..28
    const int rl = tid >> 3;        // 0..31

    u64 acc[4][SN];
    #pragma unroll
    for (int p = 0; p < 4; p++)
        #pragma unroll
        for (int j = 0; j < SN; j++) acc[p][j] = 0ull;

    for (int k0 = 0; k0 < KK; k0 += 32) {
        // A tile (128 x 32) -> [k][l]
        #pragma unroll
        for (int it = 0; it < 4; it++) {
            int row = rl + it * 32;
            float4 v = *(const float4*)&A[(size_t)(r0 + row) * KK + k0 + k4];
            as[k4 + 0][row] = v.x;
            as[k4 + 1][row] = v.y;
            as[k4 + 2][row] = v.z;
            as[k4 + 3][row] = v.w;
        }
        // B tile (NT x 32) -> [k][h]
        #pragma unroll
        for (int it = 0; it < NT / 32; it++) {
            int h = rl + it * 32;
            float4 v = *(const float4*)&B[(size_t)(h0 + h) * KK + k0 + k4];
            bs[k4 + 0][h] = v.x;
            bs[k4 + 1][h] = v.y;
            bs[k4 + 2][h] = v.z;
            bs[k4 + 3][h] = v.w;
        }
        __syncthreads();

        #pragma unroll 8
        for (int kk = 0; kk < 32; kk++) {
            ulonglong2 a01 = *(const ulonglong2*)&as[kk][tr * 8];
            ulonglong2 a23 = *(const ulonglong2*)&as[kk][tr * 8 + 4];
            u64 ap[4] = {a01.x, a01.y, a23.x, a23.y};
            #pragma unroll
            for (int jq = 0; jq < SN / 4; jq++) {
                float4 bv = *(const float4*)&bs[kk][tc * SN + jq * 4];
                u64 b0 = pack2(bv.x, bv.x);
                u64 b1 = pack2(bv.y, bv.y);
                u64 b2 = pack2(bv.z, bv.z);
                u64 b3 = pack2(bv.w, bv.w);
                #pragma unroll
                for (int p = 0; p < 4; p++) {
                    acc[p][jq * 4 + 0] = ffma2(ap[p], b0, acc[p][jq * 4 + 0]);
                    acc[p][jq * 4 + 1] = ffma2(ap[p], b1, acc[p][jq * 4 + 1]);
                    acc[p][jq * 4 + 2] = ffma2(ap[p], b2, acc[p][jq * 4 + 2]);
                    acc[p][jq * 4 + 3] = ffma2(ap[p], b3, acc[p][jq * 4 + 3]);
                }
            }
        }
        __syncthreads();
    }

    #pragma unroll
    for (int jq = 0; jq < SN / 4; jq++) {
        float4 bb = *(const float4*)&bias[h0 + tc * SN + jq * 4];
        #pragma unroll
        for (int p = 0; p < 4; p++) {
            float2 f0 = unpack2(acc[p][jq * 4 + 0]);
            float2 f1 = unpack2(acc[p][jq * 4 + 1]);
            float2 f2 = unpack2(acc[p][jq * 4 + 2]);
            float2 f3 = unpack2(acc[p][jq * 4 + 3]);
            int row0 = r0 + tr * 8 + 2 * p;
            float4 o0 = make_float4(f0.x + bb.x, f1.x + bb.y, f2.x + bb.z, f3.x + bb.w);
            float4 o1 = make_float4(f0.y + bb.x, f1.y + bb.y, f2.y + bb.z, f3.y + bb.w);
            *(float4*)&C[(size_t)row0 * Hout + h0 + tc * SN + jq * 4] = o0;
            *(float4*)&C[(size_t)(row0 + 1) * Hout + h0 + tc * SN + jq * 4] = o1;
        }
    }
}

// ---------------------------------------------------------------------------
// Split c1 into c_point (l2-normalized) / c_value, regrouped layout [m][s][32]
// ---------------------------------------------------------------------------
__global__ __launch_bounds__(256) void center_norm_kernel()
{
    int w    = (blockIdx.x * blockDim.x + threadIdx.x) >> 5;  // 0..8191
    int lane = threadIdx.x & 31;
    int m = w >> 8;
    int s = w & 255;
    int n = m >> 3, f = m & 7;

    const float* row = &g_c1[((size_t)(n * SS + s)) * H2 + f * 64];
    float p = row[lane];
    float v = row[32 + lane];

    float sq = p * p;
    #pragma unroll
    for (int off = 16; off; off >>= 1)
        sq += __shfl_xor_sync(0xffffffffu, sq, off);

    float d = fmaxf(sqrtf(sq), 1e-12f);
    size_t o = ((size_t)(m * SS + s)) * SCn + lane;
    g_cpN[o] = p / d;
    g_cv [o] = v;
}

// ---------------------------------------------------------------------------
// Fused sim + argmax + gather, register-tiled:
// block = (m, 128-l tile), 256 threads. 8l x 4s micro-tile, K=32 resident.
// s processed in 2 smem halves x 2 register chunks of 64. unroll-8 inner.
// ---------------------------------------------------------------------------
__global__ __launch_bounds__(256, 2) void sim_dispatch3(
    const float* __restrict__ alpha_p, const float* __restrict__ beta_p)
{
    __shared__ __align__(16) float xs[32][132];   // [k][l] normalized x
    __shared__ __align__(16) float cs[32][132];   // [k][s-half]
    __shared__ float smv[128];
    __shared__ int   sms[128];

    const int m  = blockIdx.y;
    const int n  = m >> 3, f = m & 7;
    const int l0 = blockIdx.x * 128;
    const int tid  = threadIdx.x;
    const int warp = tid >> 5;
    const int lane = tid & 31;
    const int tc = tid & 15;
    const int tr = tid >> 4;

    // load + l2-normalize 128 x-rows (one warp per 16 rows, lane = k)
    #pragma unroll 4
    for (int i = 0; i < 16; i++) {
        int row = warp * 16 + i;
        float x = g_x0p[((size_t)(n * LL + l0 + row)) * HH + f * SCn + lane];
        float sq = x * x;
        #pragma unroll
        for (int off = 16; off; off >>= 1)
            sq += __shfl_xor_sync(0xffffffffu, sq, off);
        xs[lane][row] = x / fmaxf(sqrtf(sq), 1e-12f);
    }

    const float alpha = alpha_p[0];
    const float beta  = beta_p[0];

    float vbest[8];
    int   sbest[8];
    #pragma unroll
    for (int r = 0; r < 8; r++) { vbest[r] = -INFINITY; sbest[r] = 0; }

    const float* cpm = &g_cpN[(size_t)m * SS * SCn];

    #pragma unroll 1
    for (int half = 0; half < 2; half++) {
        __syncthreads();   // first pass: xs ready; later: cs no longer read
        // load 128-s half of c_point, transposed to [k][s]
        const float* cph = cpm + half * 128 * SCn;
        #pragma unroll
        for (int it = 0; it < 16; it++) {
            int idx = tid + it * 256;
            cs[idx & 31][idx >> 5] = cph[idx];
        }
        __syncthreads();

        #pragma unroll 1
        for (int chunk = 0; chunk < 2; chunk++) {
            const int sbase = half * 128 + chunk * 64 + tc * 4;
            u64 acc[4][4];
            #pragma unroll
            for (int p = 0; p < 4; p++)
                #pragma unroll
                for (int j = 0; j < 4; j++) acc[p][j] = 0ull;

            #pragma unroll 8
            for (int kk = 0; kk < 32; kk++) {
                ulonglong2 a01 = *(const ulonglong2*)&xs[kk][tr * 8];
                ulonglong2 a23 = *(const ulonglong2*)&xs[kk][tr * 8 + 4];
                float4 bv = *(const float4*)&cs[kk][chunk * 64 + tc * 4];
                u64 ap[4] = {a01.x, a01.y, a23.x, a23.y};
                u64 b0 = pack2(bv.x, bv.x);
                u64 b1 = pack2(bv.y, bv.y);
                u64 b2 = pack2(bv.z, bv.z);
                u64 b3 = pack2(bv.w, bv.w);
                #pragma unroll
                for (int p = 0; p < 4; p++) {
                    acc[p][0] = ffma2(ap[p], b0, acc[p][0]);
                    acc[p][1] = ffma2(ap[p], b1, acc[p][1]);
                    acc[p][2] = ffma2(ap[p], b2, acc[p][2]);
                    acc[p][3] = ffma2(ap[p], b3, acc[p][3]);
                }
            }

            // affine + running argmax (sigmoid applied once at the end)
            #pragma unroll
            for (int p = 0; p < 4; p++) {
                #pragma unroll
                for (int j = 0; j < 4; j++) {
                    float2 f2 = unpack2(acc[p][j]);
                    float v0 = fmaf(alpha, f2.x, beta);
                    float v1 = fmaf(alpha, f2.y, beta);
                    int s = sbase + j;
                    if (v0 > vbest[2 * p])     { vbest[2 * p] = v0;     sbest[2 * p] = s; }
                    if (v1 > vbest[2 * p + 1]) { vbest[2 * p + 1] = v1; sbest[2 * p + 1] = s; }
                }
            }
        }
    }

    // reduce across the 16 tc-threads sharing each l-row (16-lane groups)
    #pragma unroll
    for (int r = 0; r < 8; r++) {
        #pragma unroll
        for (int off = 8; off; off >>= 1) {
            float v2 = __shfl_xor_sync(0xffffffffu, vbest[r], off);
            int   s2 = __shfl_xor_sync(0xffffffffu, sbest[r], off);
            if (v2 > vbest[r] || (v2 == vbest[r] && s2 < sbest[r])) {
                vbest[r] = v2; sbest[r] = s2;
            }
        }
    }
    if (tc == 0) {
        #pragma unroll
        for (int r = 0; r < 8; r++) {
            int row = tr * 8 + r;
            smv[row] = 1.f / (1.f + __expf(-vbest[r]));
            sms[row] = sbest[r];
        }
    }
    __syncthreads();

    // gather + scale + write dispatched (coalesced 128B rows)
    const float* cvm = &g_cv[(size_t)m * SS * SCn];
    #pragma unroll
    for (int it = 0; it < 16; it++) {
        int idx = tid + it * 256;
        int row = idx >> 5, k = idx & 31;
        float out = smv[row] * __ldg(&cvm[sms[row] * SCn + k]);
        g_disp[((size_t)(n * LL + l0 + row)) * HH + f * SCn + k] = out;
    }
}

// ---------------------------------------------------------------------------
extern "C" void kernel_launch(void* const* d_in, const int* in_sizes, int n_in,
                              void* d_out, int out_size)
{
    const float* x0      = (const float*)d_in[0];
    const float* center1 = (const float*)d_in[1];
    const float* W0      = (const float*)d_in[2];
    const float* b0      = (const float*)d_in[3];
    const float* W1      = (const float*)d_in[4];
    const float* b1      = (const float*)d_in[5];
    const float* Wm      = (const float*)d_in[6];
    const float* bm      = (const float*)d_in[7];
    const float* alpha   = (const float*)d_in[8];
    const float* beta    = (const float*)d_in[9];
    float* out           = (float*)d_out;

    float* c1p;   cudaGetSymbolAddress((void**)&c1p,  g_c1);
    float* x0pp;  cudaGetSymbolAddress((void**)&x0pp, g_x0p);
    float* dispp; cudaGetSymbolAddress((void**)&dispp, g_disp);

    // K1: c1 = center1 @ W1^T + b1   (1024 x 512 x 256), small -> 64-wide N
    gemm_nt<64><<<dim3(1024 / 128, H2 / 64), 256>>>(center1, W1, b1, c1p, H2);

    // K1b: normalize c_point, split c_value
    center_norm_kernel<<<1024, 256>>>();

    // K2: x0p = x0 @ W0^T + b0       (16384 x 256 x 256), one full wave
    gemm_nt<128><<<dim3((NB * LL) / 128, HH / 128), 256>>>(x0, W0, b0, x0pp, HH);

    // K3: normalize + sim + argmax + sigmoid + gather -> dispatched
    sim_dispatch3<<<dim3(LL / 128, MM), 256>>>(alpha, beta);

    // K4: out = dispatched @ Wm^T + bm  (16384 x 256 x 256), one full wave
    gemm_nt<128><<<dim3((NB * LL) / 128, HH / 128), 256>>>(dispp, Wm, bm, out, HH);
}

// round 6
// speedup vs baseline: 1.7926x; 1.2966x over previous
#include <cuda_runtime.h>
#include <math.h>
#include <stdint.h>

// Problem constants
#define NB   4
#define LL   4096
#define SS   256
#define HH   256
#define FCn  8
#define SCn  32
#define MM   32      // NB*FCn
#define H2   512
#define KK   256     // inner dim of dense GEMMs

typedef unsigned long long u64;

// Scratch (device globals; no dynamic allocation allowed)
__device__ float g_c1[NB * SS * H2];        // center1 @ W1^T + b1   (2 MB)
__device__ float g_cpN[MM * SS * SCn];      // normalized c_point    (1 MB)
__device__ float g_cv [MM * SS * SCn];      // c_value               (1 MB)
__device__ float g_x0p[NB * LL * HH];       // x0 @ W0^T + b0        (16.8 MB)
__device__ float g_disp[NB * LL * HH];      // dispatched            (16.8 MB)

// ---------------------------------------------------------------------------
// PTX helpers
// ---------------------------------------------------------------------------
__device__ __forceinline__ u64 ffma2(u64 a, u64 b, u64 c) {
    u64 d;
    asm("fma.rn.f32x2 %0, %1, %2, %3;" : "=l"(d) : "l"(a), "l"(b), "l"(c));
    return d;
}
__device__ __forceinline__ u64 pack2(float x, float y) {
    u64 r;
    asm("mov.b64 %0, {%1, %2};" : "=l"(r) : "f"(x), "f"(y));
    return r;
}
__device__ __forceinline__ float2 unpack2(u64 v) {
    float2 f;
    asm("mov.b64 {%0, %1}, %2;" : "=f"(f.x), "=f"(f.y) : "l"(v));
    return f;
}
__device__ __forceinline__ uint32_t f2tf32(float x) {
    uint32_t r;
    asm("cvt.rna.tf32.f32 %0, %1;" : "=r"(r) : "f"(x));
    return r;
}
// m16n8k8 tf32 warp MMA, D += A*B (fp32 accum)
__device__ __forceinline__ void mma8(float4& d, const uint32_t* a, const uint32_t* b) {
    asm("mma.sync.aligned.m16n8k8.row.col.f32.tf32.tf32.f32 "
        "{%0,%1,%2,%3}, {%4,%5,%6,%7}, {%8,%9}, {%0,%1,%2,%3};"
        : "+f"(d.x), "+f"(d.y), "+f"(d.z), "+f"(d.w)
        : "r"(a[0]), "r"(a[1]), "r"(a[2]), "r"(a[3]), "r"(b[0]), "r"(b[1]));
}

// ---------------------------------------------------------------------------
// Tensor-core GEMM via mma.sync tf32:
//   C[R][Hout] = A[R][256] @ B[Hout][256]^T + bias
// NPASS=1: plain tf32 (fast, ~1e-4 accuracy) — for K4.
// NPASS=3: 3xTF32 hi/lo compensation (~fp32 accuracy) — for K2.
// Block tile 128x64, 8 warps (4m x 2n), warp tile 32x32 (2x4 m16n8 tiles).
// ---------------------------------------------------------------------------
template<int NPASS>
__global__ __launch_bounds__(256, 2) void gemm_mma(
    const float* __restrict__ A, const float* __restrict__ B,
    const float* __restrict__ bias, float* __restrict__ C, int Hout)
{
    extern __shared__ __align__(16) uint32_t msm[];
    uint32_t* Ah = msm;                                   // [128][36]
    uint32_t* Al = Ah + 4608;                             // NPASS==3 only
    uint32_t* Bh = (NPASS == 3) ? (Al + 4608) : (Ah + 4608);  // [64][36]
    uint32_t* Bl = Bh + 2304;                             // NPASS==3 only

    const int tid  = threadIdx.x;
    const int wid  = tid >> 5;
    const int lane = tid & 31;
    const int g  = lane >> 2;
    const int tg = lane & 3;
    const int mbase = (wid & 3) * 32;
    const int nbase = (wid >> 2) * 32;
    const int r0 = blockIdx.x * 128;
    const int h0 = blockIdx.y * 64;

    float4 acc[2][4];
    #pragma unroll
    for (int i = 0; i < 2; i++)
        #pragma unroll
        for (int j = 0; j < 4; j++) acc[i][j] = make_float4(0.f, 0.f, 0.f, 0.f);

    for (int c = 0; c < 8; c++) {
        __syncthreads();
        // A chunk: 128 rows x 32 k, split into tf32 hi (+lo)
        #pragma unroll
        for (int it = 0; it < 4; it++) {
            int idx = tid + it * 256;
            int row = idx >> 3, j = idx & 7;
            float4 v = *(const float4*)&A[(size_t)(r0 + row) * 256 + c * 32 + j * 4];
            uint32_t base = row * 36 + j * 4;
            float xs[4] = {v.x, v.y, v.z, v.w};
            #pragma unroll
            for (int t = 0; t < 4; t++) {
                uint32_t hi = f2tf32(xs[t]);
                Ah[base + t] = hi;
                if constexpr (NPASS == 3)
                    Al[base + t] = f2tf32(xs[t] - __uint_as_float(hi));
            }
        }
        // B chunk: 64 rows x 32 k
        #pragma unroll
        for (int it = 0; it < 2; it++) {
            int idx = tid + it * 256;
            int row = idx >> 3, j = idx & 7;
            float4 v = *(const float4*)&B[(size_t)(h0 + row) * 256 + c * 32 + j * 4];
            uint32_t base = row * 36 + j * 4;
            float xs[4] = {v.x, v.y, v.z, v.w};
            #pragma unroll
            for (int t = 0; t < 4; t++) {
                uint32_t hi = f2tf32(xs[t]);
                Bh[base + t] = hi;
                if constexpr (NPASS == 3)
                    Bl[base + t] = f2tf32(xs[t] - __uint_as_float(hi));
            }
        }
        __syncthreads();

        #pragma unroll
        for (int ks = 0; ks < 4; ks++) {
            const int k0 = ks * 8;
            uint32_t ah[2][4], bh[4][2];
            #pragma unroll
            for (int i = 0; i < 2; i++) {
                uint32_t rb = (mbase + i * 16 + g) * 36 + k0 + tg;
                ah[i][0] = Ah[rb];
                ah[i][1] = Ah[rb + 8 * 36];
                ah[i][2] = Ah[rb + 4];
                ah[i][3] = Ah[rb + 8 * 36 + 4];
            }
            #pragma unroll
            for (int j = 0; j < 4; j++) {
                uint32_t rb = (nbase + j * 8 + g) * 36 + k0 + tg;
                bh[j][0] = Bh[rb];
                bh[j][1] = Bh[rb + 4];
            }
            #pragma unroll
            for (int i = 0; i < 2; i++)
                #pragma unroll
                for (int j = 0; j < 4; j++)
                    mma8(acc[i][j], ah[i], bh[j]);

            if constexpr (NPASS == 3) {
                uint32_t bl[4][2];
                #pragma unroll
                for (int j = 0; j < 4; j++) {
                    uint32_t rb = (nbase + j * 8 + g) * 36 + k0 + tg;
                    bl[j][0] = Bl[rb];
                    bl[j][1] = Bl[rb + 4];
                }
                // hi * lo
                #pragma unroll
                for (int i = 0; i < 2; i++)
                    #pragma unroll
                    for (int j = 0; j < 4; j++)
                        mma8(acc[i][j], ah[i], bl[j]);
                // lo * hi
                uint32_t al[2][4];
                #pragma unroll
                for (int i = 0; i < 2; i++) {
                    uint32_t rb = (mbase + i * 16 + g) * 36 + k0 + tg;
                    al[i][0] = Al[rb];
                    al[i][1] = Al[rb + 8 * 36];
                    al[i][2] = Al[rb + 4];
                    al[i][3] = Al[rb + 8 * 36 + 4];
                }
                #pragma unroll
                for (int i = 0; i < 2; i++)
                    #pragma unroll
                    for (int j = 0; j < 4; j++)
                        mma8(acc[i][j], al[i], bh[j]);
            }
        }
    }

    // epilogue: bias + store (float2 per fragment row)
    #pragma unroll
    for (int j = 0; j < 4; j++) {
        int col = h0 + nbase + j * 8 + 2 * tg;
        float2 bb = *(const float2*)&bias[col];
        #pragma unroll
        for (int i = 0; i < 2; i++) {
            int row = r0 + mbase + i * 16 + g;
            float2 o0 = make_float2(acc[i][j].x + bb.x, acc[i][j].y + bb.y);
            float2 o1 = make_float2(acc[i][j].z + bb.x, acc[i][j].w + bb.y);
            *(float2*)&C[(size_t)row * Hout + col] = o0;
            *(float2*)&C[(size_t)(row + 8) * Hout + col] = o1;
        }
    }
}

// ---------------------------------------------------------------------------
// Dense fp32 GEMM (K1 only):  C[R][Hout] = A[R][256] @ B[Hout][256]^T + bias
// ---------------------------------------------------------------------------
template<int NT>
__global__ __launch_bounds__(256, 2) void gemm_nt(
    const float* __restrict__ A, const float* __restrict__ B,
    const float* __restrict__ bias, float* __restrict__ C, int Hout)
{
    constexpr int SN = NT / 16;
    __shared__ __align__(16) float as[32][132];
    __shared__ __align__(16) float bs[32][NT + 4];

    const int r0 = blockIdx.x * 128;
    const int h0 = blockIdx.y * NT;
    const int tid = threadIdx.x;
    const int tc = tid & 15;
    const int tr = tid >> 4;
    const int k4 = (tid & 7) * 4;
    const int rl = tid >> 3;

    u64 acc[4][SN];
    #pragma unroll
    for (int p = 0; p < 4; p++)
        #pragma unroll
        for (int j = 0; j < SN; j++) acc[p][j] = 0ull;

    for (int k0 = 0; k0 < KK; k0 += 32) {
        #pragma unroll
        for (int it = 0; it < 4; it++) {
            int row = rl + it * 32;
            float4 v = *(const float4*)&A[(size_t)(r0 + row) * KK + k0 + k4];
            as[k4 + 0][row] = v.x;
            as[k4 + 1][row] = v.y;
            as[k4 + 2][row] = v.z;
            as[k4 + 3][row] = v.w;
        }
        #pragma unroll
        for (int it = 0; it < NT / 32; it++) {
            int h = rl + it * 32;
            float4 v = *(const float4*)&B[(size_t)(h0 + h) * KK + k0 + k4];
            bs[k4 + 0][h] = v.x;
            bs[k4 + 1][h] = v.y;
            bs[k4 + 2][h] = v.z;
            bs[k4 + 3][h] = v.w;
        }
        __syncthreads();

        #pragma unroll 8
        for (int kk = 0; kk < 32; kk++) {
            ulonglong2 a01 = *(const ulonglong2*)&as[kk][tr * 8];
            ulonglong2 a23 = *(const ulonglong2*)&as[kk][tr * 8 + 4];
            u64 ap[4] = {a01.x, a01.y, a23.x, a23.y};
            #pragma unroll
            for (int jq = 0; jq < SN / 4; jq++) {
                float4 bv = *(const float4*)&bs[kk][tc * SN + jq * 4];
                u64 b0 = pack2(bv.x, bv.x);
                u64 b1 = pack2(bv.y, bv.y);
                u64 b2 = pack2(bv.z, bv.z);
                u64 b3 = pack2(bv.w, bv.w);
                #pragma unroll
                for (int p = 0; p < 4; p++) {
                    acc[p][jq * 4 + 0] = ffma2(ap[p], b0, acc[p][jq * 4 + 0]);
                    acc[p][jq * 4 + 1] = ffma2(ap[p], b1, acc[p][jq * 4 + 1]);
                    acc[p][jq * 4 + 2] = ffma2(ap[p], b2, acc[p][jq * 4 + 2]);
                    acc[p][jq * 4 + 3] = ffma2(ap[p], b3, acc[p][jq * 4 + 3]);
                }
            }
        }
        __syncthreads();
    }

    #pragma unroll
    for (int jq = 0; jq < SN / 4; jq++) {
        float4 bb = *(const float4*)&bias[h0 + tc * SN + jq * 4];
        #pragma unroll
        for (int p = 0; p < 4; p++) {
            float2 f0 = unpack2(acc[p][jq * 4 + 0]);
            float2 f1 = unpack2(acc[p][jq * 4 + 1]);
            float2 f2 = unpack2(acc[p][jq * 4 + 2]);
            float2 f3 = unpack2(acc[p][jq * 4 + 3]);
            int row0 = r0 + tr * 8 + 2 * p;
            float4 o0 = make_float4(f0.x + bb.x, f1.x + bb.y, f2.x + bb.z, f3.x + bb.w);
            float4 o1 = make_float4(f0.y + bb.x, f1.y + bb.y, f2.y + bb.z, f3.y + bb.w);
            *(float4*)&C[(size_t)row0 * Hout + h0 + tc * SN + jq * 4] = o0;
            *(float4*)&C[(size_t)(row0 + 1) * Hout + h0 + tc * SN + jq * 4] = o1;
        }
    }
}

// ---------------------------------------------------------------------------
// Split c1 into c_point (l2-normalized) / c_value, regrouped layout [m][s][32]
// ---------------------------------------------------------------------------
__global__ __launch_bounds__(256) void center_norm_kernel()
{
    int w    = (blockIdx.x * blockDim.x + threadIdx.x) >> 5;
    int lane = threadIdx.x & 31;
    int m = w >> 8;
    int s = w & 255;
    int n = m >> 3, f = m & 7;

    const float* row = &g_c1[((size_t)(n * SS + s)) * H2 + f * 64];
    float p = row[lane];
    float v = row[32 + lane];

    float sq = p * p;
    #pragma unroll
    for (int off = 16; off; off >>= 1)
        sq += __shfl_xor_sync(0xffffffffu, sq, off);

    float d = fmaxf(sqrtf(sq), 1e-12f);
    size_t o = ((size_t)(m * SS + s)) * SCn + lane;
    g_cpN[o] = p / d;
    g_cv [o] = v;
}

// ---------------------------------------------------------------------------
// Fused sim + argmax + gather. All 256 centers resident in smem (dyn, 51200B).
// block = (m, 128-l tile), 256 threads. 8l x 4s micro, 4 barrier-free s-chunks.
// ---------------------------------------------------------------------------
#define XS_STRIDE 132
#define CS_STRIDE 260
__global__ __launch_bounds__(256, 2) void sim_dispatch4(
    const float* __restrict__ alpha_p, const float* __restrict__ beta_p)
{
    extern __shared__ __align__(16) float dsm[];
    float* xs  = dsm;                          // [32][132]
    float* cs  = dsm + 32 * XS_STRIDE;         // [32][260]
    float* smv = cs + 32 * CS_STRIDE;          // [128]
    int*   sms = (int*)(smv + 128);            // [128]

    const int m  = blockIdx.y;
    const int n  = m >> 3, f = m & 7;
    const int l0 = blockIdx.x * 128;
    const int tid  = threadIdx.x;
    const int warp = tid >> 5;
    const int lane = tid & 31;
    const int tc = tid & 15;
    const int tr = tid >> 4;

    // load + l2-normalize 128 x-rows
    #pragma unroll 4
    for (int i = 0; i < 16; i++) {
        int row = warp * 16 + i;
        float x = g_x0p[((size_t)(n * LL + l0 + row)) * HH + f * SCn + lane];
        float sq = x * x;
        #pragma unroll
        for (int off = 16; off; off >>= 1)
            sq += __shfl_xor_sync(0xffffffffu, sq, off);
        xs[lane * XS_STRIDE + row] = x / fmaxf(sqrtf(sq), 1e-12f);
    }

    // load all 256 centers' c_point, transposed to [k][s]
    const float* cpm = &g_cpN[(size_t)m * SS * SCn];
    #pragma unroll
    for (int it = 0; it < 32; it++) {
        int idx = tid + it * 256;
        cs[(idx & 31) * CS_STRIDE + (idx >> 5)] = cpm[idx];
    }
    __syncthreads();

    const float alpha = alpha_p[0];
    const float beta  = beta_p[0];

    float vbest[8];
    int   sbest[8];
    #pragma unroll
    for (int r = 0; r < 8; r++) { vbest[r] = -INFINITY; sbest[r] = 0; }

    #pragma unroll 1
    for (int chunk = 0; chunk < 4; chunk++) {
        const int sbase = chunk * 64 + tc * 4;
        u64 acc[4][4];
        #pragma unroll
        for (int p = 0; p < 4; p++)
            #pragma unroll
            for (int j = 0; j < 4; j++) acc[p][j] = 0ull;

        #pragma unroll 8
        for (int kk = 0; kk < 32; kk++) {
            ulonglong2 a01 = *(const ulonglong2*)&xs[kk * XS_STRIDE + tr * 8];
            ulonglong2 a23 = *(const ulonglong2*)&xs[kk * XS_STRIDE + tr * 8 + 4];
            float4 bv = *(const float4*)&cs[kk * CS_STRIDE + sbase];
            u64 ap[4] = {a01.x, a01.y, a23.x, a23.y};
            u64 b0 = pack2(bv.x, bv.x);
            u64 b1 = pack2(bv.y, bv.y);
            u64 b2 = pack2(bv.z, bv.z);
            u64 b3 = pack2(bv.w, bv.w);
            #pragma unroll
            for (int p = 0; p < 4; p++) {
                acc[p][0] = ffma2(ap[p], b0, acc[p][0]);
                acc[p][1] = ffma2(ap[p], b1, acc[p][1]);
                acc[p][2] = ffma2(ap[p], b2, acc[p][2]);
                acc[p][3] = ffma2(ap[p], b3, acc[p][3]);
            }
        }

        #pragma unroll
        for (int p = 0; p < 4; p++) {
            #pragma unroll
            for (int j = 0; j < 4; j++) {
                float2 f2 = unpack2(acc[p][j]);
                float v0 = fmaf(alpha, f2.x, beta);
                float v1 = fmaf(alpha, f2.y, beta);
                int s = sbase + j;
                if (v0 > vbest[2 * p])     { vbest[2 * p] = v0;     sbest[2 * p] = s; }
                if (v1 > vbest[2 * p + 1]) { vbest[2 * p + 1] = v1; sbest[2 * p + 1] = s; }
            }
        }
    }

    // reduce across the 16 tc-threads sharing each l-row
    #pragma unroll
    for (int r = 0; r < 8; r++) {
        #pragma unroll
        for (int off = 8; off; off >>= 1) {
            float v2 = __shfl_xor_sync(0xffffffffu, vbest[r], off);
            int   s2 = __shfl_xor_sync(0xffffffffu, sbest[r], off);
            if (v2 > vbest[r] || (v2 == vbest[r] && s2 < sbest[r])) {
                vbest[r] = v2; sbest[r] = s2;
            }
        }
    }
    if (tc == 0) {
        #pragma unroll
        for (int r = 0; r < 8; r++) {
            int row = tr * 8 + r;
            smv[row] = 1.f / (1.f + __expf(-vbest[r]));
            sms[row] = sbest[r];
        }
    }
    __syncthreads();

    // gather + scale + write dispatched
    const float* cvm = &g_cv[(size_t)m * SS * SCn];
    #pragma unroll
    for (int it = 0; it < 16; it++) {
        int idx = tid + it * 256;
        int row = idx >> 5, k = idx & 31;
        float out = smv[row] * __ldg(&cvm[sms[row] * SCn + k]);
        g_disp[((size_t)(n * LL + l0 + row)) * HH + f * SCn + k] = out;
    }
}

// ---------------------------------------------------------------------------
extern "C" void kernel_launch(void* const* d_in, const int* in_sizes, int n_in,
                              void* d_out, int out_size)
{
    const float* x0      = (const float*)d_in[0];
    const float* center1 = (const float*)d_in[1];
    const float* W0      = (const float*)d_in[2];
    const float* b0      = (const float*)d_in[3];
    const float* W1      = (const float*)d_in[4];
    const float* b1      = (const float*)d_in[5];
    const float* Wm      = (const float*)d_in[6];
    const float* bm      = (const float*)d_in[7];
    const float* alpha   = (const float*)d_in[8];
    const float* beta    = (const float*)d_in[9];
    float* out           = (float*)d_out;

    float* c1p;   cudaGetSymbolAddress((void**)&c1p,  g_c1);
    float* x0pp;  cudaGetSymbolAddress((void**)&x0pp, g_x0p);
    float* dispp; cudaGetSymbolAddress((void**)&dispp, g_disp);

    const int simSmem = (32 * XS_STRIDE + 32 * CS_STRIDE + 128 + 128) * 4;  // 51200
    const int mma3Smem = (4608 * 2 + 2304 * 2) * 4;                          // 55296
    const int mma1Smem = (4608 + 2304) * 4;                                  // 27648
    cudaFuncSetAttribute(sim_dispatch4, cudaFuncAttributeMaxDynamicSharedMemorySize, simSmem);
    cudaFuncSetAttribute(gemm_mma<3>, cudaFuncAttributeMaxDynamicSharedMemorySize, mma3Smem);
    cudaFuncSetAttribute(gemm_mma<1>, cudaFuncAttributeMaxDynamicSharedMemorySize, mma1Smem);

    // K1: c1 = center1 @ W1^T + b1   (1024 x 512 x 256), fp32 FFMA2
    gemm_nt<64><<<dim3(1024 / 128, H2 / 64), 256>>>(center1, W1, b1, c1p, H2);

    // K1b: normalize c_point, split c_value
    center_norm_kernel<<<1024, 256>>>();

    // K2: x0p = x0 @ W0^T + b0  (3xTF32 mma.sync — fp32-accurate)
    gemm_mma<3><<<dim3((NB * LL) / 128, HH / 64), 256, mma3Smem>>>(x0, W0, b0, x0pp, HH);

    // K3: normalize + sim + argmax + sigmoid + gather -> dispatched
    sim_dispatch4<<<dim3(LL / 128, MM), 256, simSmem>>>(alpha, beta);

    // K4: out = dispatched @ Wm^T + bm  (single-pass tf32 mma.sync)
    gemm_mma<1><<<dim3((NB * LL) / 128, HH / 64), 256, mma1Smem>>>(dispp, Wm, bm, out, HH);
}

// round 7
// speedup vs baseline: 1.9151x; 1.0684x over previous
#include <cuda_runtime.h>
#include <math.h>
#include <stdint.h>

// Problem constants
#define NB   4
#define LL   4096
#define SS   256
#define HH   256
#define FCn  8
#define SCn  32
#define MM   32      // NB*FCn
#define H2   512
#define KK   256     // inner dim of dense GEMMs

typedef unsigned long long u64;

// Scratch (device globals; no dynamic allocation allowed)
__device__ float    g_c1[NB * SS * H2];       // center1 @ W1^T + b1   (2 MB)
__device__ uint32_t g_cpHi[MM * SS * SCn];    // tf32 hi of normalized c_point
__device__ uint32_t g_cpLo[MM * SS * SCn];    // tf32 lo residual
__device__ float    g_cv [MM * SS * SCn];     // c_value               (1 MB)
__device__ float    g_x0p[NB * LL * HH];      // x0 @ W0^T + b0        (16.8 MB)
__device__ float    g_disp[NB * LL * HH];     // dispatched            (16.8 MB)

// ---------------------------------------------------------------------------
// PTX helpers
// ---------------------------------------------------------------------------
__device__ __forceinline__ u64 ffma2(u64 a, u64 b, u64 c) {
    u64 d;
    asm("fma.rn.f32x2 %0, %1, %2, %3;" : "=l"(d) : "l"(a), "l"(b), "l"(c));
    return d;
}
__device__ __forceinline__ u64 pack2(float x, float y) {
    u64 r;
    asm("mov.b64 %0, {%1, %2};" : "=l"(r) : "f"(x), "f"(y));
    return r;
}
__device__ __forceinline__ float2 unpack2(u64 v) {
    float2 f;
    asm("mov.b64 {%0, %1}, %2;" : "=f"(f.x), "=f"(f.y) : "l"(v));
    return f;
}
__device__ __forceinline__ uint32_t f2tf32(float x) {
    uint32_t r;
    asm("cvt.rna.tf32.f32 %0, %1;" : "=r"(r) : "f"(x));
    return r;
}
// m16n8k8 tf32 warp MMA, D += A*B (fp32 accum)
__device__ __forceinline__ void mma8(float4& d, const uint32_t* a, const uint32_t* b) {
    asm("mma.sync.aligned.m16n8k8.row.col.f32.tf32.tf32.f32 "
        "{%0,%1,%2,%3}, {%4,%5,%6,%7}, {%8,%9}, {%0,%1,%2,%3};"
        : "+f"(d.x), "+f"(d.y), "+f"(d.z), "+f"(d.w)
        : "r"(a[0]), "r"(a[1]), "r"(a[2]), "r"(a[3]), "r"(b[0]), "r"(b[1]));
}

// ---------------------------------------------------------------------------
// Tensor-core GEMM via mma.sync tf32:
//   C[R][Hout] = A[R][256] @ B[Hout][256]^T + bias
// NPASS=1: plain tf32 — K4.  NPASS=3: hi/lo compensation (~fp32) — K2.
// ---------------------------------------------------------------------------
template<int NPASS>
__global__ __launch_bounds__(256, 2) void gemm_mma(
    const float* __restrict__ A, const float* __restrict__ B,
    const float* __restrict__ bias, float* __restrict__ C, int Hout)
{
    extern __shared__ __align__(16) uint32_t msm[];
    uint32_t* Ah = msm;                                   // [128][36]
    uint32_t* Al = Ah + 4608;                             // NPASS==3 only
    uint32_t* Bh = (NPASS == 3) ? (Al + 4608) : (Ah + 4608);  // [64][36]
    uint32_t* Bl = Bh + 2304;                             // NPASS==3 only

    const int tid  = threadIdx.x;
    const int wid  = tid >> 5;
    const int lane = tid & 31;
    const int g  = lane >> 2;
    const int tg = lane & 3;
    const int mbase = (wid & 3) * 32;
    const int nbase = (wid >> 2) * 32;
    const int r0 = blockIdx.x * 128;
    const int h0 = blockIdx.y * 64;

    float4 acc[2][4];
    #pragma unroll
    for (int i = 0; i < 2; i++)
        #pragma unroll
        for (int j = 0; j < 4; j++) acc[i][j] = make_float4(0.f, 0.f, 0.f, 0.f);

    for (int c = 0; c < 8; c++) {
        __syncthreads();
        #pragma unroll
        for (int it = 0; it < 4; it++) {
            int idx = tid + it * 256;
            int row = idx >> 3, j = idx & 7;
            float4 v = *(const float4*)&A[(size_t)(r0 + row) * 256 + c * 32 + j * 4];
            uint32_t base = row * 36 + j * 4;
            float xs[4] = {v.x, v.y, v.z, v.w};
            #pragma unroll
            for (int t = 0; t < 4; t++) {
                uint32_t hi = f2tf32(xs[t]);
                Ah[base + t] = hi;
                if constexpr (NPASS == 3)
                    Al[base + t] = f2tf32(xs[t] - __uint_as_float(hi));
            }
        }
        #pragma unroll
        for (int it = 0; it < 2; it++) {
            int idx = tid + it * 256;
            int row = idx >> 3, j = idx & 7;
            float4 v = *(const float4*)&B[(size_t)(h0 + row) * 256 + c * 32 + j * 4];
            uint32_t base = row * 36 + j * 4;
            float xs[4] = {v.x, v.y, v.z, v.w};
            #pragma unroll
            for (int t = 0; t < 4; t++) {
                uint32_t hi = f2tf32(xs[t]);
                Bh[base + t] = hi;
                if constexpr (NPASS == 3)
                    Bl[base + t] = f2tf32(xs[t] - __uint_as_float(hi));
            }
        }
        __syncthreads();

        #pragma unroll
        for (int ks = 0; ks < 4; ks++) {
            const int k0 = ks * 8;
            uint32_t ah[2][4], bh[4][2];
            #pragma unroll
            for (int i = 0; i < 2; i++) {
                uint32_t rb = (mbase + i * 16 + g) * 36 + k0 + tg;
                ah[i][0] = Ah[rb];
                ah[i][1] = Ah[rb + 8 * 36];
                ah[i][2] = Ah[rb + 4];
                ah[i][3] = Ah[rb + 8 * 36 + 4];
            }
            #pragma unroll
            for (int j = 0; j < 4; j++) {
                uint32_t rb = (nbase + j * 8 + g) * 36 + k0 + tg;
                bh[j][0] = Bh[rb];
                bh[j][1] = Bh[rb + 4];
            }
            #pragma unroll
            for (int i = 0; i < 2; i++)
                #pragma unroll
                for (int j = 0; j < 4; j++)
                    mma8(acc[i][j], ah[i], bh[j]);

            if constexpr (NPASS == 3) {
                uint32_t bl[4][2];
                #pragma unroll
                for (int j = 0; j < 4; j++) {
                    uint32_t rb = (nbase + j * 8 + g) * 36 + k0 + tg;
                    bl[j][0] = Bl[rb];
                    bl[j][1] = Bl[rb + 4];
                }
                #pragma unroll
                for (int i = 0; i < 2; i++)
                    #pragma unroll
                    for (int j = 0; j < 4; j++)
                        mma8(acc[i][j], ah[i], bl[j]);
                uint32_t al[2][4];
                #pragma unroll
                for (int i = 0; i < 2; i++) {
                    uint32_t rb = (mbase + i * 16 + g) * 36 + k0 + tg;
                    al[i][0] = Al[rb];
                    al[i][1] = Al[rb + 8 * 36];
                    al[i][2] = Al[rb + 4];
                    al[i][3] = Al[rb + 8 * 36 + 4];
                }
                #pragma unroll
                for (int i = 0; i < 2; i++)
                    #pragma unroll
                    for (int j = 0; j < 4; j++)
                        mma8(acc[i][j], al[i], bh[j]);
            }
        }
    }

    #pragma unroll
    for (int j = 0; j < 4; j++) {
        int col = h0 + nbase + j * 8 + 2 * tg;
        float2 bb = *(const float2*)&bias[col];
        #pragma unroll
        for (int i = 0; i < 2; i++) {
            int row = r0 + mbase + i * 16 + g;
            float2 o0 = make_float2(acc[i][j].x + bb.x, acc[i][j].y + bb.y);
            float2 o1 = make_float2(acc[i][j].z + bb.x, acc[i][j].w + bb.y);
            *(float2*)&C[(size_t)row * Hout + col] = o0;
            *(float2*)&C[(size_t)(row + 8) * Hout + col] = o1;
        }
    }
}

// ---------------------------------------------------------------------------
// Dense fp32 GEMM (K1 only)
// ---------------------------------------------------------------------------
template<int NT>
__global__ __launch_bounds__(256, 2) void gemm_nt(
    const float* __restrict__ A, const float* __restrict__ B,
    const float* __restrict__ bias, float* __restrict__ C, int Hout)
{
    constexpr int SN = NT / 16;
    __shared__ __align__(16) float as[32][132];
    __shared__ __align__(16) float bs[32][NT + 4];

    const int r0 = blockIdx.x * 128;
    const int h0 = blockIdx.y * NT;
    const int tid = threadIdx.x;
    const int tc = tid & 15;
    const int tr = tid >> 4;
    const int k4 = (tid & 7) * 4;
    const int rl = tid >> 3;

    u64 acc[4][SN];
    #pragma unroll
    for (int p = 0; p < 4; p++)
        #pragma unroll
        for (int j = 0; j < SN; j++) acc[p][j] = 0ull;

    for (int k0 = 0; k0 < KK; k0 += 32) {
        #pragma unroll
        for (int it = 0; it < 4; it++) {
            int row = rl + it * 32;
            float4 v = *(const float4*)&A[(size_t)(r0 + row) * KK + k0 + k4];
            as[k4 + 0][row] = v.x;
            as[k4 + 1][row] = v.y;
            as[k4 + 2][row] = v.z;
            as[k4 + 3][row] = v.w;
        }
        #pragma unroll
        for (int it = 0; it < NT / 32; it++) {
            int h = rl + it * 32;
            float4 v = *(const float4*)&B[(size_t)(h0 + h) * KK + k0 + k4];
            bs[k4 + 0][h] = v.x;
            bs[k4 + 1][h] = v.y;
            bs[k4 + 2][h] = v.z;
            bs[k4 + 3][h] = v.w;
        }
        __syncthreads();

        #pragma unroll 8
        for (int kk = 0; kk < 32; kk++) {
            ulonglong2 a01 = *(const ulonglong2*)&as[kk][tr * 8];
            ulonglong2 a23 = *(const ulonglong2*)&as[kk][tr * 8 + 4];
            u64 ap[4] = {a01.x, a01.y, a23.x, a23.y};
            #pragma unroll
            for (int jq = 0; jq < SN / 4; jq++) {
                float4 bv = *(const float4*)&bs[kk][tc * SN + jq * 4];
                u64 b0 = pack2(bv.x, bv.x);
                u64 b1 = pack2(bv.y, bv.y);
                u64 b2 = pack2(bv.z, bv.z);
                u64 b3 = pack2(bv.w, bv.w);
                #pragma unroll
                for (int p = 0; p < 4; p++) {
                    acc[p][jq * 4 + 0] = ffma2(ap[p], b0, acc[p][jq * 4 + 0]);
                    acc[p][jq * 4 + 1] = ffma2(ap[p], b1, acc[p][jq * 4 + 1]);
                    acc[p][jq * 4 + 2] = ffma2(ap[p], b2, acc[p][jq * 4 + 2]);
                    acc[p][jq * 4 + 3] = ffma2(ap[p], b3, acc[p][jq * 4 + 3]);
                }
            }
        }
        __syncthreads();
    }

    #pragma unroll
    for (int jq = 0; jq < SN / 4; jq++) {
        float4 bb = *(const float4*)&bias[h0 + tc * SN + jq * 4];
        #pragma unroll
        for (int p = 0; p < 4; p++) {
            float2 f0 = unpack2(acc[p][jq * 4 + 0]);
            float2 f1 = unpack2(acc[p][jq * 4 + 1]);
            float2 f2 = unpack2(acc[p][jq * 4 + 2]);
            float2 f3 = unpack2(acc[p][jq * 4 + 3]);
            int row0 = r0 + tr * 8 + 2 * p;
            float4 o0 = make_float4(f0.x + bb.x, f1.x + bb.y, f2.x + bb.z, f3.x + bb.w);
            float4 o1 = make_float4(f0.y + bb.x, f1.y + bb.y, f2.y + bb.z, f3.y + bb.w);
            *(float4*)&C[(size_t)row0 * Hout + h0 + tc * SN + jq * 4] = o0;
            *(float4*)&C[(size_t)(row0 + 1) * Hout + h0 + tc * SN + jq * 4] = o1;
        }
    }
}

// ---------------------------------------------------------------------------
// Split c1 into c_point (l2-normalized, tf32 hi/lo split) / c_value.
// ---------------------------------------------------------------------------
__global__ __launch_bounds__(256) void center_norm_kernel()
{
    int w    = (blockIdx.x * blockDim.x + threadIdx.x) >> 5;
    int lane = threadIdx.x & 31;
    int m = w >> 8;
    int s = w & 255;
    int n = m >> 3, f = m & 7;

    const float* row = &g_c1[((size_t)(n * SS + s)) * H2 + f * 64];
    float p = row[lane];
    float v = row[32 + lane];

    float sq = p * p;
    #pragma unroll
    for (int off = 16; off; off >>= 1)
        sq += __shfl_xor_sync(0xffffffffu, sq, off);

    float d = fmaxf(sqrtf(sq), 1e-12f);
    float pn = p / d;
    size_t o = ((size_t)(m * SS + s)) * SCn + lane;
    uint32_t hi = f2tf32(pn);
    g_cpHi[o] = hi;
    g_cpLo[o] = f2tf32(pn - __uint_as_float(hi));
    g_cv [o] = v;
}

// ---------------------------------------------------------------------------
// Fused sim (3xTF32 mma.sync) + argmax + sigmoid + gather.
// block = (m, 128-l tile), 256 threads, 8 warps x 16 rows.
// B (centers) in two 128-s smem halves; running argmax on fragments.
// ---------------------------------------------------------------------------
__global__ __launch_bounds__(256, 2) void sim_mma(
    const float* __restrict__ alpha_p, const float* __restrict__ beta_p)
{
    extern __shared__ __align__(16) uint32_t ssm[];
    uint32_t* Ah = ssm;                 // [128][36]
    uint32_t* Al = Ah + 128 * 36;
    uint32_t* Bh = Al + 128 * 36;       // [128][36] (s-half)
    uint32_t* Bl = Bh + 128 * 36;
    float*    smv = (float*)(Bl + 128 * 36);   // [128]
    int*      sms = (int*)(smv + 128);         // [128]

    const int m  = blockIdx.y;
    const int n  = m >> 3, f = m & 7;
    const int l0 = blockIdx.x * 128;
    const int tid  = threadIdx.x;
    const int wid  = tid >> 5;
    const int lane = tid & 31;
    const int g  = lane >> 2;
    const int tg = lane & 3;

    // A: load x0p rows, l2-normalize, tf32 hi/lo split -> smem (stride 36)
    #pragma unroll 4
    for (int i = 0; i < 16; i++) {
        int row = wid * 16 + i;
        float x = g_x0p[((size_t)(n * LL + l0 + row)) * HH + f * SCn + lane];
        float sq = x * x;
        #pragma unroll
        for (int off = 16; off; off >>= 1)
            sq += __shfl_xor_sync(0xffffffffu, sq, off);
        float xn = x / fmaxf(sqrtf(sq), 1e-12f);
        uint32_t hi = f2tf32(xn);
        Ah[row * 36 + lane] = hi;
        Al[row * 36 + lane] = f2tf32(xn - __uint_as_float(hi));
    }

    const float alpha = alpha_p[0];
    const float beta  = beta_p[0];
    const uint32_t* cph = &g_cpHi[(size_t)m * SS * SCn];
    const uint32_t* cpl = &g_cpLo[(size_t)m * SS * SCn];

    float vb[2] = {-INFINITY, -INFINITY};
    int   sb[2] = {0, 0};

    #pragma unroll 1
    for (int half = 0; half < 2; half++) {
        __syncthreads();
        // load B half (128 s x 32 k), conflict-free scalar copies
        #pragma unroll
        for (int it = 0; it < 16; it++) {
            int idx = tid + it * 256;
            int srow = idx >> 5, k = idx & 31;
            Bh[srow * 36 + k] = cph[half * 4096 + idx];
            Bl[srow * 36 + k] = cpl[half * 4096 + idx];
        }
        __syncthreads();

        #pragma unroll 1
        for (int cq = 0; cq < 2; cq++) {
            float4 acc[8];
            #pragma unroll
            for (int j = 0; j < 8; j++) acc[j] = make_float4(0.f, 0.f, 0.f, 0.f);

            #pragma unroll
            for (int ks = 0; ks < 4; ks++) {
                uint32_t rb = (wid * 16 + g) * 36 + ks * 8 + tg;
                uint32_t ahh[4] = {Ah[rb], Ah[rb + 8 * 36], Ah[rb + 4], Ah[rb + 8 * 36 + 4]};
                uint32_t alo[4] = {Al[rb], Al[rb + 8 * 36], Al[rb + 4], Al[rb + 8 * 36 + 4]};
                #pragma unroll
                for (int j = 0; j < 8; j++) {
                    uint32_t rb2 = (cq * 64 + j * 8 + g) * 36 + ks * 8 + tg;
                    uint32_t bhh[2] = {Bh[rb2], Bh[rb2 + 4]};
                    uint32_t blo[2] = {Bl[rb2], Bl[rb2 + 4]};
                    mma8(acc[j], ahh, bhh);
                    mma8(acc[j], ahh, blo);
                    mma8(acc[j], alo, bhh);
                }
            }

            // running affine argmax (increasing s order preserves tie rule)
            const int sbase = half * 128 + cq * 64;
            #pragma unroll
            for (int j = 0; j < 8; j++) {
                int s0 = sbase + j * 8 + 2 * tg;
                float v0 = fmaf(alpha, acc[j].x, beta);
                float v1 = fmaf(alpha, acc[j].y, beta);
                float v2 = fmaf(alpha, acc[j].z, beta);
                float v3 = fmaf(alpha, acc[j].w, beta);
                if (v0 > vb[0]) { vb[0] = v0; sb[0] = s0; }
                if (v1 > vb[0]) { vb[0] = v1; sb[0] = s0 + 1; }
                if (v2 > vb[1]) { vb[1] = v2; sb[1] = s0; }
                if (v3 > vb[1]) { vb[1] = v3; sb[1] = s0 + 1; }
            }
        }
    }

    // reduce argmax across the 4 tg-lanes of each quad (rows g / g+8)
    #pragma unroll
    for (int r = 0; r < 2; r++) {
        #pragma unroll
        for (int off = 1; off < 4; off <<= 1) {
            float v2 = __shfl_xor_sync(0xffffffffu, vb[r], off);
            int   s2 = __shfl_xor_sync(0xffffffffu, sb[r], off);
            if (v2 > vb[r] || (v2 == vb[r] && s2 < sb[r])) { vb[r] = v2; sb[r] = s2; }
        }
    }
    if (tg == 0) {
        int row0 = wid * 16 + g;
        smv[row0]     = 1.f / (1.f + __expf(-vb[0]));
        sms[row0]     = sb[0];
        smv[row0 + 8] = 1.f / (1.f + __expf(-vb[1]));
        sms[row0 + 8] = sb[1];
    }
    __syncthreads();

    // gather + scale + write dispatched
    const float* cvm = &g_cv[(size_t)m * SS * SCn];
    #pragma unroll
    for (int it = 0; it < 16; it++) {
        int idx = tid + it * 256;
        int row = idx >> 5, k = idx & 31;
        float out = smv[row] * __ldg(&cvm[sms[row] * SCn + k]);
        g_disp[((size_t)(n * LL + l0 + row)) * HH + f * SCn + k] = out;
    }
}

// ---------------------------------------------------------------------------
extern "C" void kernel_launch(void* const* d_in, const int* in_sizes, int n_in,
                              void* d_out, int out_size)
{
    const float* x0      = (const float*)d_in[0];
    const float* center1 = (const float*)d_in[1];
    const float* W0      = (const float*)d_in[2];
    const float* b0      = (const float*)d_in[3];
    const float* W1      = (const float*)d_in[4];
    const float* b1      = (const float*)d_in[5];
    const float* Wm      = (const float*)d_in[6];
    const float* bm      = (const float*)d_in[7];
    const float* alpha   = (const float*)d_in[8];
    const float* beta    = (const float*)d_in[9];
    float* out           = (float*)d_out;

    float* c1p;   cudaGetSymbolAddress((void**)&c1p,  g_c1);
    float* x0pp;  cudaGetSymbolAddress((void**)&x0pp, g_x0p);
    float* dispp; cudaGetSymbolAddress((void**)&dispp, g_disp);

    const int simSmem  = 4 * 128 * 36 * 4 + 128 * 8;   // 74752
    const int mma3Smem = (4608 * 2 + 2304 * 2) * 4;    // 55296
    const int mma1Smem = (4608 + 2304) * 4;            // 27648
    cudaFuncSetAttribute(sim_mma, cudaFuncAttributeMaxDynamicSharedMemorySize, simSmem);
    cudaFuncSetAttribute(gemm_mma<3>, cudaFuncAttributeMaxDynamicSharedMemorySize, mma3Smem);
    cudaFuncSetAttribute(gemm_mma<1>, cudaFuncAttributeMaxDynamicSharedMemorySize, mma1Smem);

    // K1: c1 = center1 @ W1^T + b1   (1024 x 512 x 256), fp32 FFMA2
    gemm_nt<64><<<dim3(1024 / 128, H2 / 64), 256>>>(center1, W1, b1, c1p, H2);

    // K1b: normalize c_point (tf32 hi/lo split), split c_value
    center_norm_kernel<<<1024, 256>>>();

    // K2: x0p = x0 @ W0^T + b0  (3xTF32 mma.sync — fp32-accurate)
    gemm_mma<3><<<dim3((NB * LL) / 128, HH / 64), 256, mma3Smem>>>(x0, W0, b0, x0pp, HH);

    // K3: sim (3xTF32 mma.sync) + argmax + sigmoid + gather -> dispatched
    sim_mma<<<dim3(LL / 128, MM), 256, simSmem>>>(alpha, beta);

    // K4: out = dispatched @ Wm^T + bm  (single-pass tf32 mma.sync)
    gemm_mma<1><<<dim3((NB * LL) / 128, HH / 64), 256, mma1Smem>>>(dispp, Wm, bm, out, HH);
}